// round 17
// baseline (speedup 1.0000x reference)
#include <cuda_runtime.h>
#include <cuda_fp16.h>
#include <cstdint>

// value[b] = -( x[b] . MLP(x[b]) )^2 — fp16 HMMA GEMM chain.
// R17: M_CTA=128 for L1/L2 (grid 512) -> W L2 traffic halved, fewer CP16/MMA.
//      All weights single fp16. L3+L4 fused kernel unchanged (M=64).

__device__ __half g_Whi[442368];
__device__ __half g_actA[65536UL * 512];
__device__ __half g_actB[65536UL * 512];

__device__ __forceinline__ uint32_t smem_u32(const void* p) {
    uint32_t a;
    asm("{ .reg .u64 t; cvta.to.shared.u64 t, %1; cvt.u32.u64 %0, t; }" : "=r"(a) : "l"(p));
    return a;
}
__device__ __forceinline__ void ldsm4(uint32_t* r, uint32_t addr) {
    asm volatile("ldmatrix.sync.aligned.m8n8.x4.shared.b16 {%0,%1,%2,%3}, [%4];"
        : "=r"(r[0]), "=r"(r[1]), "=r"(r[2]), "=r"(r[3]) : "r"(addr));
}
__device__ __forceinline__ void mma_f16(float* c, const uint32_t* a, const uint32_t* b) {
    asm volatile("mma.sync.aligned.m16n8k16.row.col.f32.f16.f16.f32 "
        "{%0,%1,%2,%3}, {%4,%5,%6,%7}, {%8,%9}, {%0,%1,%2,%3};"
        : "+f"(c[0]), "+f"(c[1]), "+f"(c[2]), "+f"(c[3])
        : "r"(a[0]), "r"(a[1]), "r"(a[2]), "r"(a[3]), "r"(b[0]), "r"(b[1]));
}
#define CP16(dst, src)  asm volatile("cp.async.cg.shared.global [%0], [%1], 16;" :: "r"(dst), "l"(src))
#define CP_COMMIT()     asm volatile("cp.async.commit_group;" ::: "memory")
#define CP_WAIT0()      asm volatile("cp.async.wait_group 0;" ::: "memory")

__device__ __forceinline__ uint32_t packh2(__half a, __half b) {
    return (uint32_t)__half_as_ushort(a) | ((uint32_t)__half_as_ushort(b) << 16);
}

__global__ void split_all(const float* __restrict__ W1, const float* __restrict__ W2,
                          const float* __restrict__ W3, const float* __restrict__ W4) {
    int i = blockIdx.x * blockDim.x + threadIdx.x;
    if (i >= 442368) return;
    float w;
    if (i < 32768)       w = W1[i];
    else if (i < 294912) w = W2[i - 32768];
    else if (i < 425984) w = W3[i - 294912];
    else                 w = W4[i - 425984];
    g_Whi[i] = __float2half_rn(w);
}

// ============================ Layer 1: x(f32,K=64) -> 512, ELU. M_CTA=128 ============================
// smem: [0,16384) x tile (128 rows x 128B) | [16384,49152) W bufs 2x16K | [49152,51200) bias
__global__ void __launch_bounds__(256, 2)
l1_kernel(const float* __restrict__ x, const float* __restrict__ bias,
          __half* __restrict__ out)
{
    extern __shared__ char sm[];
    constexpr int WOFF = 16384, BIAS = 49152;
    const int tid = threadIdx.x, wid = tid >> 5, l = tid & 31;
    const long base = (long)blockIdx.x * 128;
    const uint32_t smb = smem_u32(sm);

    const int pr = tid >> 3, pc = tid & 7;
    const uint32_t swz = ((uint32_t)(pc ^ (pr & 7)) << 4);
    const __half* wS = g_Whi + pr * 64 + pc * 8;          // + nt*8192 + j*2048
    const uint32_t wD = smb + WOFF + pr * 128 + swz;      // + buf*16384 + j*4096

    auto prefW = [&](int nt, int buf) {
        const __half* s = wS + nt * 8192;
        const uint32_t d = wD + buf * 16384;
        #pragma unroll
        for (int j = 0; j < 4; j++) CP16(d + j * 4096, s + j * 2048);
    };

    prefW(0, 0); CP_COMMIT();

    // x tile: 128 rows x 64 cols fp32 -> fp16 swizzled
    #pragma unroll
    for (int i = tid; i < 2048; i += 256) {
        const int r = i >> 4, k4 = (i & 15) * 4;
        const int c = k4 >> 3, wi = (k4 & 4) << 1;
        const float4 v = *(const float4*)(x + (base + r) * 64 + k4);
        const uint32_t off = r * 128 + ((uint32_t)(c ^ (r & 7)) << 4) + wi;
        *(uint32_t*)(sm + off)     = packh2(__float2half_rn(v.x), __float2half_rn(v.y));
        *(uint32_t*)(sm + off + 4) = packh2(__float2half_rn(v.z), __float2half_rn(v.w));
    }
    for (int i = tid; i < 512; i += 256) *(float*)(sm + BIAS + i * 4) = bias[i];

    // 4M x 2N warps: M=32/warp, N=64/warp within the 128-wide n-tile
    const int wM = (wid & 3) * 32, wN = (wid >> 2) * 64;
    const int aRow = wM + (l & 15), aCk = l >> 4;
    const uint32_t aSel = (uint32_t)(aRow & 7);
    const int bnLoc = (l & 7) | ((l & 16) >> 1), bcLoc = (l >> 3) & 1;

    #pragma unroll 2
    for (int nt = 0; nt < 4; nt++) {
        CP_WAIT0();
        __syncthreads();
        if (nt + 1 < 4) { prefW(nt + 1, (nt + 1) & 1); CP_COMMIT(); }
        const uint32_t wb = smb + WOFF + (nt & 1) * 16384;

        float acc[64];
        #pragma unroll
        for (int q = 0; q < 64; q++) acc[q] = 0.0f;

        #pragma unroll
        for (int s = 0; s < 4; s++) {
            const int ck = s * 2 + aCk;
            uint32_t ah[2][4];
            #pragma unroll
            for (int mt = 0; mt < 2; mt++)
                ldsm4(ah[mt], smb + (aRow + mt * 16) * 128 + ((uint32_t)(ck ^ aSel) << 4));
            const int bc = s * 2 + bcLoc;
            uint32_t bh[8][2], t[4];
            #pragma unroll
            for (int pp = 0; pp < 4; pp++) {
                const int n = wN + 16 * pp + bnLoc;
                const uint32_t ba = wb + n * 128 + ((uint32_t)(bc ^ (n & 7)) << 4);
                ldsm4(t, ba);
                bh[2*pp][0]=t[0]; bh[2*pp][1]=t[1]; bh[2*pp+1][0]=t[2]; bh[2*pp+1][1]=t[3];
            }
            #pragma unroll
            for (int mt = 0; mt < 2; mt++) {
                float* am = acc + mt * 32;
                #pragma unroll
                for (int u = 0; u < 8; u++) mma_f16(am + 4*u, ah[mt], bh[u]);
            }
        }
        #pragma unroll
        for (int mt = 0; mt < 2; mt++) {
            const int r0 = wM + mt * 16 + (l >> 2);
            #pragma unroll
            for (int j = 0; j < 8; j++) {
                const int col = nt * 128 + wN + j * 8 + (l & 3) * 2;
                const float b0 = *(const float*)(sm + BIAS + col * 4);
                const float b1 = *(const float*)(sm + BIAS + col * 4 + 4);
                const int q = mt * 32 + j * 4;
                float v00 = acc[q+0] + b0, v01 = acc[q+1] + b1;
                float v10 = acc[q+2] + b0, v11 = acc[q+3] + b1;
                v00 = v00 > 0.f ? v00 : expm1f(v00);
                v01 = v01 > 0.f ? v01 : expm1f(v01);
                v10 = v10 > 0.f ? v10 : expm1f(v10);
                v11 = v11 > 0.f ? v11 : expm1f(v11);
                *(uint32_t*)(out + (base + r0) * 512 + col)     = packh2(__float2half_rn(v00), __float2half_rn(v01));
                *(uint32_t*)(out + (base + r0 + 8) * 512 + col) = packh2(__float2half_rn(v10), __float2half_rn(v11));
            }
        }
    }
}

// ============================ Layer 2: K=512 -> 512 (ELU). M_CTA=128 ============================
// smem: [0,32768) A bufs 2x16K | [32768,65536) W bufs 2x16K | [65536,67584) bias
__global__ void __launch_bounds__(256, 2)
mid512_kernel(const __half* __restrict__ in, const float* __restrict__ bias,
              __half* __restrict__ out)
{
    extern __shared__ char sm[];
    constexpr int WOFFS = 32768, BIAS = 65536, NITER = 32;

    const int tid = threadIdx.x, wid = tid >> 5, l = tid & 31;
    const long base = (long)blockIdx.x * 128;
    const uint32_t smb = smem_u32(sm);

    const int pr = tid >> 3, pc = tid & 7;
    const uint32_t swz = ((uint32_t)(pc ^ (pr & 7)) << 4);
    const __half* aS = in + (base + pr) * 512 + pc * 8;            // + kt*64 + j*16384
    const uint32_t aD = smb + pr * 128 + swz;                      // + buf*16384 + j*4096
    const __half* wS = g_Whi + 32768 + (long)pr * 512 + pc * 8;    // + ng*65536 + kt*64 + j*16384
    const uint32_t wD = smb + WOFFS + pr * 128 + swz;              // + buf*16384 + j*4096

    auto prefetch = [&](int it, int buf) {
        const int ng = it >> 3, kt = it & 7;
        const __half* as = aS + kt * 64;
        const uint32_t ad = aD + buf * 16384;
        #pragma unroll
        for (int j = 0; j < 4; j++) CP16(ad + j * 4096, as + j * 16384);
        const __half* ws = wS + ng * 65536 + kt * 64;
        const uint32_t wd = wD + buf * 16384;
        #pragma unroll
        for (int j = 0; j < 4; j++) CP16(wd + j * 4096, ws + j * 16384);
    };

    prefetch(0, 0); CP_COMMIT();
    for (int i = tid; i < 512; i += 256) *(float*)(sm + BIAS + i * 4) = bias[i];

    const int wM = (wid & 3) * 32, wN = (wid >> 2) * 64;
    const int aRow = wM + (l & 15), aCk = l >> 4;
    const uint32_t aSel = (uint32_t)(aRow & 7);
    const int bnLoc = (l & 7) | ((l & 16) >> 1), bcLoc = (l >> 3) & 1;

    float acc[64];

    #pragma unroll 1
    for (int ng = 0; ng < 4; ++ng) {
        #pragma unroll
        for (int q = 0; q < 64; q++) acc[q] = 0.0f;

        #pragma unroll 2
        for (int kt = 0; kt < 8; ++kt) {
            const int it = ng * 8 + kt;
            CP_WAIT0();
            __syncthreads();
            if (it + 1 < NITER) { prefetch(it + 1, (kt + 1) & 1); CP_COMMIT(); }
            const uint32_t ab = smb + (kt & 1) * 16384;
            const uint32_t wb = smb + WOFFS + (kt & 1) * 16384;
            #pragma unroll
            for (int s = 0; s < 4; s++) {
                const int ck = s * 2 + aCk;
                uint32_t ah[2][4];
                #pragma unroll
                for (int mt = 0; mt < 2; mt++)
                    ldsm4(ah[mt], ab + (aRow + mt * 16) * 128 + ((uint32_t)(ck ^ aSel) << 4));
                const int bc = s * 2 + bcLoc;
                uint32_t bh[8][2], t[4];
                #pragma unroll
                for (int pp = 0; pp < 4; pp++) {
                    const int n = wN + 16 * pp + bnLoc;
                    const uint32_t ba = wb + n * 128 + ((uint32_t)(bc ^ (n & 7)) << 4);
                    ldsm4(t, ba);
                    bh[2*pp][0]=t[0]; bh[2*pp][1]=t[1]; bh[2*pp+1][0]=t[2]; bh[2*pp+1][1]=t[3];
                }
                #pragma unroll
                for (int mt = 0; mt < 2; mt++) {
                    float* am = acc + mt * 32;
                    #pragma unroll
                    for (int u = 0; u < 8; u++) mma_f16(am + 4*u, ah[mt], bh[u]);
                }
            }
        }
        #pragma unroll
        for (int mt = 0; mt < 2; mt++) {
            const int r0 = wM + mt * 16 + (l >> 2);
            #pragma unroll
            for (int j = 0; j < 8; j++) {
                const int col = ng * 128 + wN + j * 8 + (l & 3) * 2;
                const float b0 = *(const float*)(sm + BIAS + col * 4);
                const float b1 = *(const float*)(sm + BIAS + col * 4 + 4);
                const int q = mt * 32 + j * 4;
                float v00 = acc[q+0] + b0, v01 = acc[q+1] + b1;
                float v10 = acc[q+2] + b0, v11 = acc[q+3] + b1;
                v00 = v00 > 0.f ? v00 : expm1f(v00);
                v01 = v01 > 0.f ? v01 : expm1f(v01);
                v10 = v10 > 0.f ? v10 : expm1f(v10);
                v11 = v11 > 0.f ? v11 : expm1f(v11);
                *(uint32_t*)(out + (base + r0) * 512 + col)     = packh2(__float2half_rn(v00), __float2half_rn(v01));
                *(uint32_t*)(out + (base + r0 + 8) * 512 + col) = packh2(__float2half_rn(v10), __float2half_rn(v11));
            }
        }
    }
}

// ============================ Fused L3+L4: K=512 -> 256 (ELU) -> 64 -> -(x.z)^2 (M=64) ============================
__global__ void __launch_bounds__(256, 2)
l34_kernel(const __half* __restrict__ in, const float* __restrict__ bias3,
           const float* __restrict__ bias4, const float* __restrict__ x,
           float* __restrict__ outv)
{
    extern __shared__ char sm[];
    constexpr int KT = 8, WOFF3 = 294912, WOFF4 = 425984;
    constexpr int ACT3 = 16384, W4OFF = 49152, BIAS3 = 81920, BIAS4 = 82944, ZSUM = 83200;

    const int tid = threadIdx.x, wid = tid >> 5, l = tid & 31;
    const long base = (long)blockIdx.x * 64;
    const uint32_t smb = smem_u32(sm);

    const int pr = tid >> 3, pc = tid & 7;
    const uint32_t swz = ((uint32_t)(pc ^ (pr & 7)) << 4);
    const __half* aS = in + (base + pr) * 512 + pc * 8;
    const uint32_t aD = smb + pr * 128 + swz;
    const __half* w3S = g_Whi + WOFF3 + (long)pr * 512 + pc * 8;
    const uint32_t w3D = smb + 16384 + pr * 128 + swz;
    const __half* w4S = g_Whi + WOFF4 + pr * 256 + pc * 8;
    const uint32_t w4D = smb + W4OFF + pr * 512 + ((uint32_t)(pc ^ (pr & 7)) << 4);

    auto prefetch = [&](int kt, int buf) {
        const __half* as = aS + kt * 64;
        const uint32_t ad = aD + buf * 8192;
        CP16(ad,        as);
        CP16(ad + 4096, as + 16384);
        const __half* ws = w3S + kt * 64;
        const uint32_t wd = w3D + buf * 32768;
        #pragma unroll
        for (int j = 0; j < 8; j++) CP16(wd + j * 4096, ws + j * 16384);
    };

    prefetch(0, 0); CP_COMMIT();
    for (int i = tid; i < 256; i += 256) *(float*)(sm + BIAS3 + i * 4) = bias3[i];
    if (tid < 64) *(float*)(sm + BIAS4 + tid * 4) = bias4[tid];

    const int wM = (wid & 1) * 32, wN = (wid >> 1) * 32;
    const int aRow = wM + (l & 15), aCk = l >> 4;
    const uint32_t aSel = (uint32_t)(aRow & 7);
    const int bnLoc = (l & 7) | ((l & 16) >> 1), bcLoc = (l >> 3) & 1;

    float acc[64];
    #pragma unroll
    for (int q = 0; q < 64; q++) acc[q] = 0.0f;

    #pragma unroll 2
    for (int kt = 0; kt < KT; ++kt) {
        CP_WAIT0();
        __syncthreads();
        if (kt + 1 < KT) { prefetch(kt + 1, (kt + 1) & 1); CP_COMMIT(); }
        const uint32_t ab = smb + (kt & 1) * 8192;
        const uint32_t wb = smb + 16384 + (kt & 1) * 32768;
        #pragma unroll
        for (int s = 0; s < 4; s++) {
            const int ck = s * 2 + aCk;
            uint32_t ah[2][4];
            #pragma unroll
            for (int mt = 0; mt < 2; mt++)
                ldsm4(ah[mt], ab + (aRow + mt * 16) * 128 + ((uint32_t)(ck ^ aSel) << 4));
            const int bc = s * 2 + bcLoc;
            uint32_t bh[8][2], t[4];
            #pragma unroll
            for (int tl = 0; tl < 2; tl++) {
                #pragma unroll
                for (int pp = 0; pp < 2; pp++) {
                    const int n = tl * 128 + wN + 16 * pp + bnLoc;
                    const uint32_t ba = wb + n * 128 + ((uint32_t)(bc ^ (n & 7)) << 4);
                    ldsm4(t, ba);
                    bh[tl*4 + 2*pp][0]=t[0]; bh[tl*4 + 2*pp][1]=t[1];
                    bh[tl*4 + 2*pp+1][0]=t[2]; bh[tl*4 + 2*pp+1][1]=t[3];
                }
            }
            #pragma unroll
            for (int mt = 0; mt < 2; mt++) {
                float* am = acc + mt * 32;
                #pragma unroll
                for (int u = 0; u < 8; u++) mma_f16(am + 4*u, ah[mt], bh[u]);
            }
        }
    }

    __syncthreads();

    #pragma unroll
    for (int r2 = 0; r2 < 2; r2++) {
        #pragma unroll
        for (int k = 0; k < 4; k++)
            CP16(w4D + r2 * 16384 + k * 128, w4S + r2 * 8192 + k * 64);
    }
    CP_COMMIT();

    #pragma unroll
    for (int mt = 0; mt < 2; mt++) {
        const int r0 = wM + mt * 16 + (l >> 2);
        #pragma unroll
        for (int tl = 0; tl < 2; tl++) {
            #pragma unroll
            for (int j = 0; j < 4; j++) {
                const int col = tl * 128 + wN + j * 8 + (l & 3) * 2;
                const float b0 = *(const float*)(sm + BIAS3 + col * 4);
                const float b1 = *(const float*)(sm + BIAS3 + col * 4 + 4);
                const int q = mt * 32 + tl * 16 + j * 4;
                float v00 = acc[q+0] + b0, v01 = acc[q+1] + b1;
                float v10 = acc[q+2] + b0, v11 = acc[q+3] + b1;
                v00 = v00 > 0.f ? v00 : expm1f(v00);
                v01 = v01 > 0.f ? v01 : expm1f(v01);
                v10 = v10 > 0.f ? v10 : expm1f(v10);
                v11 = v11 > 0.f ? v11 : expm1f(v11);
                const int c16 = col >> 3;
                const int wi = (col & 7) * 2;
                const uint32_t a0 = ACT3 + r0 * 512 + ((uint32_t)(c16 ^ (r0 & 7)) << 4) + wi;
                const uint32_t a1 = ACT3 + (r0 + 8) * 512 + ((uint32_t)(c16 ^ ((r0 + 8) & 7)) << 4) + wi;
                *(uint32_t*)(sm + a0) = packh2(__float2half_rn(v00), __float2half_rn(v01));
                *(uint32_t*)(sm + a1) = packh2(__float2half_rn(v10), __float2half_rn(v11));
            }
        }
    }
    CP_WAIT0();
    __syncthreads();

    const int wN4 = (wid >> 1) * 16;
    float acc4[16];
    #pragma unroll
    for (int q = 0; q < 16; q++) acc4[q] = 0.0f;

    #pragma unroll
    for (int s = 0; s < 16; s++) {
        const int ckk = s * 2 + aCk;
        uint32_t ah[2][4];
        #pragma unroll
        for (int mt = 0; mt < 2; mt++)
            ldsm4(ah[mt], smb + ACT3 + (aRow + mt * 16) * 512 + ((uint32_t)(ckk ^ aSel) << 4));
        const int bc = s * 2 + bcLoc;
        uint32_t bh[2][2], t[4];
        {
            const int n = wN4 + bnLoc;
            const uint32_t ba = smb + W4OFF + n * 512 + ((uint32_t)(bc ^ (n & 7)) << 4);
            ldsm4(t, ba);
            bh[0][0]=t[0]; bh[0][1]=t[1]; bh[1][0]=t[2]; bh[1][1]=t[3];
        }
        #pragma unroll
        for (int mt = 0; mt < 2; mt++) {
            float* am = acc4 + mt * 8;
            mma_f16(am + 0, ah[mt], bh[0]);
            mma_f16(am + 4, ah[mt], bh[1]);
        }
    }

    float* zsum = (float*)(sm + ZSUM);
    #pragma unroll
    for (int mt = 0; mt < 2; mt++) {
        const int r0 = wM + mt * 16 + (l >> 2);
        float p0 = 0.0f, p1 = 0.0f;
        #pragma unroll
        for (int u = 0; u < 2; u++) {
            const int col = wN4 + u * 8 + (l & 3) * 2;
            const float b0 = *(const float*)(sm + BIAS4 + col * 4);
            const float b1 = *(const float*)(sm + BIAS4 + col * 4 + 4);
            const int q = mt * 8 + u * 4;
            const float2 x0 = *(const float2*)(x + (base + r0) * 64 + col);
            const float2 x1 = *(const float2*)(x + (base + r0 + 8) * 64 + col);
            p0 += (acc4[q+0] + b0) * x0.x + (acc4[q+1] + b1) * x0.y;
            p1 += (acc4[q+2] + b0) * x1.x + (acc4[q+3] + b1) * x1.y;
        }
        p0 += __shfl_xor_sync(0xFFFFFFFF, p0, 1);
        p0 += __shfl_xor_sync(0xFFFFFFFF, p0, 2);
        p1 += __shfl_xor_sync(0xFFFFFFFF, p1, 1);
        p1 += __shfl_xor_sync(0xFFFFFFFF, p1, 2);
        if ((l & 3) == 0) {
            zsum[r0 * 4 + (wid >> 1)]       = p0;
            zsum[(r0 + 8) * 4 + (wid >> 1)] = p1;
        }
    }
    __syncthreads();
    if (tid < 64) {
        const float s = zsum[tid * 4] + zsum[tid * 4 + 1] + zsum[tid * 4 + 2] + zsum[tid * 4 + 3];
        outv[base + tid] = -s * s;
    }
}

extern "C" void kernel_launch(void* const* d_in, const int* in_sizes, int n_in,
                              void* d_out, int out_size)
{
    const float* x  = (const float*)d_in[0];
    const float* W1 = (const float*)d_in[1];
    const float* b1 = (const float*)d_in[2];
    const float* W2 = (const float*)d_in[3];
    const float* b2 = (const float*)d_in[4];
    const float* W3 = (const float*)d_in[5];
    const float* b3 = (const float*)d_in[6];
    const float* W4 = (const float*)d_in[7];
    const float* b4 = (const float*)d_in[8];
    float* out = (float*)d_out;

    __half *actA, *actB;
    cudaGetSymbolAddress((void**)&actA, g_actA);
    cudaGetSymbolAddress((void**)&actB, g_actB);

    split_all<<<(442368 + 511) / 512, 512>>>(W1, W2, W3, W4);

    constexpr int SZ1 = 51200;    // 16K x + 32K W bufs + 2K bias
    constexpr int SZM = 67584;    // 32K A bufs + 32K W bufs + 2K bias
    constexpr int SZ34 = 84224;
    cudaFuncSetAttribute(l1_kernel,     cudaFuncAttributeMaxDynamicSharedMemorySize, SZ1);
    cudaFuncSetAttribute(mid512_kernel, cudaFuncAttributeMaxDynamicSharedMemorySize, SZM);
    cudaFuncSetAttribute(l34_kernel,    cudaFuncAttributeMaxDynamicSharedMemorySize, SZ34);

    l1_kernel<<<512, 256, SZ1>>>(x, b1, actA);
    mid512_kernel<<<512, 256, SZM>>>(actA, b2, actB);
    l34_kernel<<<1024, 256, SZ34>>>(actB, b3, b4, x, out);
}